// round 1
// baseline (speedup 1.0000x reference)
#include <cuda_runtime.h>
#include <math.h>

#define B_ROWS   16384
#define DATA_DIM 4096
#define Z_DIM    512
#define H_DIM    400

// ---------------- scratch (allocation-free: device globals) ----------------
__device__ float g_h1[B_ROWS * H_DIM];   // 26.2 MB
__device__ float g_z [B_ROWS * Z_DIM];   // 33.5 MB
__device__ float g_h3[B_ROWS * H_DIM];   // 26.2 MB
__device__ float g_std[B_ROWS];

// ---------------- generic SGEMM: C[M,N] = epi(A[M,K] @ B[K,N] + bias) ------
// M is always 16384 (multiple of 128). K is always a multiple of 8 and N a
// multiple of 4, so only the N-tile edge needs guarding (N=400 case).
// EPI: 0 = identity, 1 = relu, 2 = sigmoid
template <int EPI>
__global__ __launch_bounds__(256, 2) void sgemm_bias(
    const float* __restrict__ A, const float* __restrict__ Bm,
    const float* __restrict__ bias, float* __restrict__ C,
    int N, int K)
{
    __shared__ float As[8][128];
    __shared__ float Bs[8][128];

    const int tid = threadIdx.x;
    const int bx  = blockIdx.x;          // N tile
    const int by  = blockIdx.y;          // M tile
    const int tx  = tid & 15;            // 0..15
    const int ty  = tid >> 4;            // 0..15

    const float* Ab = A + (size_t)by * 128 * K;
    const int bcol0 = bx * 128;

    // A tile loader: 128 rows x 8 cols, one float4 per thread
    const int arow  = tid >> 1;          // 0..127
    const int acol4 = (tid & 1) * 4;     // 0 or 4
    // B tile loader: 8 rows x 128 cols, one float4 per thread
    const int brow  = tid >> 5;          // 0..7
    const int bcol4 = (tid & 31) * 4;    // 0..124

    float acc[8][8];
#pragma unroll
    for (int i = 0; i < 8; i++)
#pragma unroll
        for (int j = 0; j < 8; j++) acc[i][j] = 0.0f;

    for (int k0 = 0; k0 < K; k0 += 8) {
        // load A tile (transposed into smem for coalesced compute reads)
        float4 av = *reinterpret_cast<const float4*>(
            Ab + (size_t)arow * K + (k0 + acol4));
        As[acol4 + 0][arow] = av.x;
        As[acol4 + 1][arow] = av.y;
        As[acol4 + 2][arow] = av.z;
        As[acol4 + 3][arow] = av.w;

        // load B tile
        float4 bv = make_float4(0.f, 0.f, 0.f, 0.f);
        const int gc = bcol0 + bcol4;
        if (gc < N)
            bv = *reinterpret_cast<const float4*>(
                Bm + (size_t)(k0 + brow) * N + gc);
        *reinterpret_cast<float4*>(&Bs[brow][bcol4]) = bv;

        __syncthreads();

#pragma unroll
        for (int k = 0; k < 8; k++) {
            float4 a0 = *reinterpret_cast<const float4*>(&As[k][ty * 8]);
            float4 a1 = *reinterpret_cast<const float4*>(&As[k][ty * 8 + 4]);
            float4 b0 = *reinterpret_cast<const float4*>(&Bs[k][tx * 8]);
            float4 b1 = *reinterpret_cast<const float4*>(&Bs[k][tx * 8 + 4]);
            float ra[8] = {a0.x, a0.y, a0.z, a0.w, a1.x, a1.y, a1.z, a1.w};
            float rb[8] = {b0.x, b0.y, b0.z, b0.w, b1.x, b1.y, b1.z, b1.w};
#pragma unroll
            for (int i = 0; i < 8; i++)
#pragma unroll
                for (int j = 0; j < 8; j++)
                    acc[i][j] = fmaf(ra[i], rb[j], acc[i][j]);
        }
        __syncthreads();
    }

    // epilogue: bias + activation + guarded store
#pragma unroll
    for (int i = 0; i < 8; i++) {
        const size_t gr = (size_t)by * 128 + ty * 8 + i;
#pragma unroll
        for (int j = 0; j < 8; j++) {
            const int gc = bcol0 + tx * 8 + j;
            if (gc < N) {
                float v = acc[i][j] + bias[gc];
                if (EPI == 1) v = fmaxf(v, 0.0f);
                if (EPI == 2) v = 1.0f / (1.0f + expf(-v));
                C[gr * N + gc] = v;
            }
        }
    }
}

// ------------- per-row heads: rho = tanh(h1@W22+b22), logs = h1@W23+b23 ----
__global__ void rho_logs_kernel(const float* __restrict__ h1,
                                const float* __restrict__ W22,
                                const float* __restrict__ b22,
                                const float* __restrict__ W23,
                                const float* __restrict__ b23,
                                float* __restrict__ rho_out,
                                float* __restrict__ logs_out)
{
    const int row  = blockIdx.x * blockDim.y + threadIdx.y;
    const int lane = threadIdx.x;
    const float* hr = h1 + (size_t)row * H_DIM;

    float a = 0.f, b = 0.f;
    for (int i = lane; i < H_DIM; i += 32) {
        const float h = hr[i];
        a = fmaf(h, W22[i], a);
        b = fmaf(h, W23[i], b);
    }
#pragma unroll
    for (int o = 16; o > 0; o >>= 1) {
        a += __shfl_xor_sync(0xffffffffu, a, o);
        b += __shfl_xor_sync(0xffffffffu, b, o);
    }
    if (lane == 0) {
        const float logs = b + b23[0];
        rho_out[row]  = tanhf(a + b22[0]);
        logs_out[row] = logs;
        g_std[row]    = sqrtf(expf(logs));
    }
}

// ------------- z = cumsum(eps * std, axis=1) + mu  (block-per-row scan) ----
__global__ void scan_kernel(const float* __restrict__ eps,
                            const float* __restrict__ mu,
                            float* __restrict__ z)
{
    const int row = blockIdx.x;
    const int t   = threadIdx.x;          // 0..511, 16 warps
    const float s = g_std[row];

    float v = eps[(size_t)row * Z_DIM + t] * s;

    // warp inclusive scan
#pragma unroll
    for (int o = 1; o < 32; o <<= 1) {
        const float n = __shfl_up_sync(0xffffffffu, v, o);
        if ((t & 31) >= o) v += n;
    }
    __shared__ float ws[16];
    if ((t & 31) == 31) ws[t >> 5] = v;
    __syncthreads();
    if (t < 16) {
        float w = ws[t];
#pragma unroll
        for (int o = 1; o < 16; o <<= 1) {
            const float n = __shfl_up_sync(0x0000ffffu, w, o);
            if (t >= o) w += n;
        }
        ws[t] = w;
    }
    __syncthreads();
    if (t >= 32) v += ws[(t >> 5) - 1];

    z[(size_t)row * Z_DIM + t] = v + mu[(size_t)row * Z_DIM + t];
}

// ---------------------------------------------------------------------------
extern "C" void kernel_launch(void* const* d_in, const int* in_sizes, int n_in,
                              void* d_out, int out_size)
{
    const float* x   = (const float*)d_in[0];
    const float* eps = (const float*)d_in[1];
    const float* W1  = (const float*)d_in[2];
    const float* b1  = (const float*)d_in[3];
    const float* W21 = (const float*)d_in[4];
    const float* b21 = (const float*)d_in[5];
    const float* W22 = (const float*)d_in[6];
    const float* b22 = (const float*)d_in[7];
    const float* W23 = (const float*)d_in[8];
    const float* b23 = (const float*)d_in[9];
    const float* W3  = (const float*)d_in[10];
    const float* b3  = (const float*)d_in[11];
    const float* W4  = (const float*)d_in[12];
    const float* b4  = (const float*)d_in[13];

    float* out       = (float*)d_out;
    float* out_recon = out;                                        // [B, 4096]
    float* out_mu    = out_recon + (size_t)B_ROWS * DATA_DIM;      // [B, 512]
    float* out_rho   = out_mu    + (size_t)B_ROWS * Z_DIM;         // [B, 1]
    float* out_logs  = out_rho   + B_ROWS;                         // [B, 1]

    float *h1, *z, *h3;
    cudaGetSymbolAddress((void**)&h1, g_h1);
    cudaGetSymbolAddress((void**)&z,  g_z);
    cudaGetSymbolAddress((void**)&h3, g_h3);

    const dim3 blk(256);

    // 1) h1 = relu(x @ W1 + b1)                     [16384,4096]x[4096,400]
    sgemm_bias<1><<<dim3((H_DIM + 127) / 128, B_ROWS / 128), blk>>>(
        x, W1, b1, h1, H_DIM, DATA_DIM);

    // 2a) rho / logs / std (warp per row)
    rho_logs_kernel<<<B_ROWS / 8, dim3(32, 8)>>>(
        h1, W22, b22, W23, b23, out_rho, out_logs);

    // 2b) mu = h1 @ W21 + b21                       [16384,400]x[400,512]
    sgemm_bias<0><<<dim3(Z_DIM / 128, B_ROWS / 128), blk>>>(
        h1, W21, b21, out_mu, Z_DIM, H_DIM);

    // 2c) z = cumsum(eps*std) + mu
    scan_kernel<<<B_ROWS, Z_DIM>>>(eps, out_mu, z);

    // 3) h3 = relu(z @ W3 + b3)                     [16384,512]x[512,400]
    sgemm_bias<1><<<dim3((H_DIM + 127) / 128, B_ROWS / 128), blk>>>(
        z, W3, b3, h3, H_DIM, Z_DIM);

    // 4) recon = sigmoid(h3 @ W4 + b4)              [16384,400]x[400,4096]
    sgemm_bias<2><<<dim3(DATA_DIM / 128, B_ROWS / 128), blk>>>(
        h3, W4, b4, out_recon, DATA_DIM, H_DIM);
}

// round 4
// speedup vs baseline: 2.1735x; 2.1735x over previous
#include <cuda_runtime.h>
#include <cuda_bf16.h>
#include <cstdint>
#include <math.h>

#define B_ROWS   16384
#define DATA_DIM 4096
#define Z_DIM    512
#define H_DIM    400
#define H_PAD    448     // H padded to multiple of 32 (K use)
#define N1_PAD   512     // H padded to multiple of 128 (N-tile use)

typedef __nv_bfloat16 bf16;

// ---------------- scratch (allocation-free device globals, zero-init) ------
__device__ alignas(256) bf16 g_xh [B_ROWS * DATA_DIM];
__device__ alignas(256) bf16 g_xl [B_ROWS * DATA_DIM];
__device__ alignas(256) bf16 g_h1h[B_ROWS * H_PAD];    // pad cols stay zero
__device__ alignas(256) bf16 g_h1l[B_ROWS * H_PAD];
__device__ alignas(256) bf16 g_zh [B_ROWS * Z_DIM];
__device__ alignas(256) bf16 g_zl [B_ROWS * Z_DIM];
__device__ alignas(256) bf16 g_h3h[B_ROWS * H_PAD];
__device__ alignas(256) bf16 g_h3l[B_ROWS * H_PAD];
__device__ float g_std[B_ROWS];
// transposed + split weights [Npad][Kpad] bf16 (K-major), zero padded
__device__ alignas(256) bf16 g_W1h [N1_PAD * DATA_DIM], g_W1l [N1_PAD * DATA_DIM];
__device__ alignas(256) bf16 g_W21h[Z_DIM * H_PAD],     g_W21l[Z_DIM * H_PAD];
__device__ alignas(256) bf16 g_W3h [N1_PAD * Z_DIM],    g_W3l [N1_PAD * Z_DIM];
__device__ alignas(256) bf16 g_W4h [DATA_DIM * H_PAD],  g_W4l [DATA_DIM * H_PAD];

// ---------------- PTX helpers ----------------------------------------------
__device__ __forceinline__ uint32_t smem_u32(const void* p) {
    uint32_t a;
    asm("{ .reg .u64 t; cvta.to.shared.u64 t, %1; cvt.u32.u64 %0, t; }"
        : "=r"(a) : "l"(p));
    return a;
}
__device__ __forceinline__ void cp16(uint32_t dst, const void* src) {
    asm volatile("cp.async.cg.shared.global [%0], [%1], 16;"
                 :: "r"(dst), "l"(src) : "memory");
}
__device__ __forceinline__ void cp_commit() {
    asm volatile("cp.async.commit_group;" ::: "memory");
}
template <int N> __device__ __forceinline__ void cp_wait() {
    asm volatile("cp.async.wait_group %0;" :: "n"(N) : "memory");
}
#define LDSM4(R, addr) \
    asm volatile("ldmatrix.sync.aligned.m8n8.x4.shared.b16 {%0,%1,%2,%3}, [%4];" \
                 : "=r"((R)[0]), "=r"((R)[1]), "=r"((R)[2]), "=r"((R)[3])      \
                 : "r"(addr))
#define MMA16816(C, A, B0, B1) \
    asm volatile("mma.sync.aligned.m16n8k16.row.col.f32.bf16.bf16.f32 "        \
                 "{%0,%1,%2,%3}, {%4,%5,%6,%7}, {%8,%9}, {%0,%1,%2,%3};"       \
                 : "+f"((C)[0]), "+f"((C)[1]), "+f"((C)[2]), "+f"((C)[3])      \
                 : "r"((A)[0]), "r"((A)[1]), "r"((A)[2]), "r"((A)[3]),         \
                   "r"(B0), "r"(B1))

// smem stage layout: 4 matrices [128 rows][40 bf16] (80 B rows, 16B aligned)
#define ROWB     80
#define MAT_SZ   10240                 // 128*80
#define OFF_AH   0
#define OFF_AL   10240
#define OFF_BH   20480
#define OFF_BL   30720
#define STAGE_SZ 40960
#define SMEM_TOT (2 * STAGE_SZ)

// ---------------- stage loader (cp.async, 16B chunks) ----------------------
__device__ __forceinline__ void ld_stage(
    uint32_t s0, int tid,
    const bf16* __restrict__ Ah, const bf16* __restrict__ Al,
    size_t arow0, int lda,
    const bf16* __restrict__ Bh, const bf16* __restrict__ Bl,
    size_t brow0, int ldb, int k0)
{
#pragma unroll
    for (int j = 0; j < 8; j++) {
        const int arr = j >> 1;                 // 0:Ah 1:Al 2:Bh 3:Bl
        const int idx = tid + (j & 1) * 256;    // 0..511
        const int row = idx >> 2;               // 0..127
        const int ch  = idx & 3;                // 16B chunk in row
        const bf16* src;
        if (arr == 0)      src = Ah + (arow0 + row) * (size_t)lda + k0 + ch * 8;
        else if (arr == 1) src = Al + (arow0 + row) * (size_t)lda + k0 + ch * 8;
        else if (arr == 2) src = Bh + (brow0 + row) * (size_t)ldb + k0 + ch * 8;
        else               src = Bl + (brow0 + row) * (size_t)ldb + k0 + ch * 8;
        cp16(s0 + arr * MAT_SZ + row * ROWB + ch * 16, src);
    }
}

// ---------------- split-bf16 tensor-core GEMM ------------------------------
// C[128*by.., 128*bx..] = epi(A @ B^T + bias)
// A: bf16 hi/lo [M][lda] row-major; B: bf16 hi/lo [Npad][ldb] K-major.
// EPI: 0 none, 1 relu, 2 sigmoid.  SPLIT: 1 -> store hi/lo bf16, 0 -> fp32.
template <int EPI, int SPLIT>
__global__ __launch_bounds__(256) void gemm_mma(
    const bf16* __restrict__ Ah, const bf16* __restrict__ Al, int lda,
    const bf16* __restrict__ Bh, const bf16* __restrict__ Bl, int ldb,
    const float* __restrict__ bias,
    float* __restrict__ Cf, bf16* __restrict__ Ch, bf16* __restrict__ Cl,
    int ldc, int nout, int K)
{
    extern __shared__ char smem[];
    const uint32_t sb = smem_u32(smem);
    const int tid  = threadIdx.x;
    const int wid  = tid >> 5, lane = tid & 31;
    const int wm   = wid & 1,  wn   = wid >> 1;   // 2 M-warps x 4 N-warps
    const int bx   = blockIdx.x, by = blockIdx.y;
    const size_t arow0 = (size_t)by * 128;
    const size_t brow0 = (size_t)bx * 128;

    float acc[4][4][4];
#pragma unroll
    for (int a = 0; a < 4; a++)
#pragma unroll
        for (int b = 0; b < 4; b++)
#pragma unroll
            for (int c = 0; c < 4; c++) acc[a][b][c] = 0.0f;

    const int NC = K >> 5;
    ld_stage(sb, tid, Ah, Al, arow0, lda, Bh, Bl, brow0, ldb, 0);
    cp_commit();

    for (int i = 0; i < NC; i++) {
        if (i + 1 < NC) {
            ld_stage(sb + ((i + 1) & 1) * STAGE_SZ, tid,
                     Ah, Al, arow0, lda, Bh, Bl, brow0, ldb, (i + 1) << 5);
            cp_commit();
            cp_wait<1>();
        } else {
            cp_wait<0>();
        }
        __syncthreads();

        const uint32_t st = sb + (i & 1) * STAGE_SZ;
#pragma unroll
        for (int ks = 0; ks < 2; ks++) {
            const int k16 = ks * 16;
            uint32_t ah[4][4], al[4][4], bh[4][2], bl[4][2];
#pragma unroll
            for (int mt = 0; mt < 4; mt++) {
                const int row = wm * 64 + mt * 16 + (lane & 15);
                const uint32_t aoff = row * ROWB + k16 * 2 + ((lane >> 4) << 4);
                LDSM4(ah[mt], st + OFF_AH + aoff);
                LDSM4(al[mt], st + OFF_AL + aoff);
            }
#pragma unroll
            for (int nt = 0; nt < 2; nt++) {
                const int row = wn * 32 + nt * 16 + (lane & 7) + ((lane >> 4) << 3);
                const uint32_t boff = row * ROWB + (k16 + ((lane >> 3) & 1) * 8) * 2;
                uint32_t r[4];
                LDSM4(r, st + OFF_BH + boff);
                bh[nt * 2][0] = r[0]; bh[nt * 2][1] = r[1];
                bh[nt * 2 + 1][0] = r[2]; bh[nt * 2 + 1][1] = r[3];
                LDSM4(r, st + OFF_BL + boff);
                bl[nt * 2][0] = r[0]; bl[nt * 2][1] = r[1];
                bl[nt * 2 + 1][0] = r[2]; bl[nt * 2 + 1][1] = r[3];
            }
#pragma unroll
            for (int mt = 0; mt < 4; mt++)
#pragma unroll
                for (int n = 0; n < 4; n++) {
                    MMA16816(acc[mt][n], ah[mt], bh[n][0], bh[n][1]);
                    MMA16816(acc[mt][n], al[mt], bh[n][0], bh[n][1]);
                    MMA16816(acc[mt][n], ah[mt], bl[n][0], bl[n][1]);
                }
        }
        __syncthreads();
    }

    // ---- epilogue: bias + activation, direct register stores ----
#pragma unroll
    for (int n8 = 0; n8 < 4; n8++) {
        const int gc = bx * 128 + wn * 32 + n8 * 8 + (lane & 3) * 2;
        if (gc >= nout) continue;
        const float bia0 = bias[gc], bia1 = bias[gc + 1];
#pragma unroll
        for (int mt = 0; mt < 4; mt++) {
            const size_t r0 = arow0 + wm * 64 + mt * 16 + (lane >> 2);
            float v[4];
            v[0] = acc[mt][n8][0] + bia0;  v[1] = acc[mt][n8][1] + bia1;
            v[2] = acc[mt][n8][2] + bia0;  v[3] = acc[mt][n8][3] + bia1;
#pragma unroll
            for (int q = 0; q < 4; q++) {
                if (EPI == 1) v[q] = fmaxf(v[q], 0.0f);
                if (EPI == 2) v[q] = 1.0f / (1.0f + __expf(-v[q]));
            }
            if (SPLIT) {
                bf16 h0 = __float2bfloat16_rn(v[0]);
                bf16 h1 = __float2bfloat16_rn(v[1]);
                bf16 h2 = __float2bfloat16_rn(v[2]);
                bf16 h3 = __float2bfloat16_rn(v[3]);
                __nv_bfloat162 hp0, hp1, lp0, lp1;
                hp0.x = h0; hp0.y = h1;  hp1.x = h2; hp1.y = h3;
                lp0.x = __float2bfloat16_rn(v[0] - __bfloat162float(h0));
                lp0.y = __float2bfloat16_rn(v[1] - __bfloat162float(h1));
                lp1.x = __float2bfloat16_rn(v[2] - __bfloat162float(h2));
                lp1.y = __float2bfloat16_rn(v[3] - __bfloat162float(h3));
                *reinterpret_cast<__nv_bfloat162*>(Ch + r0 * ldc + gc)       = hp0;
                *reinterpret_cast<__nv_bfloat162*>(Cl + r0 * ldc + gc)       = lp0;
                *reinterpret_cast<__nv_bfloat162*>(Ch + (r0 + 8) * ldc + gc) = hp1;
                *reinterpret_cast<__nv_bfloat162*>(Cl + (r0 + 8) * ldc + gc) = lp1;
            } else {
                float2 p0, p1;
                p0.x = v[0]; p0.y = v[1];  p1.x = v[2]; p1.y = v[3];
                *reinterpret_cast<float2*>(Cf + r0 * ldc + gc)       = p0;
                *reinterpret_cast<float2*>(Cf + (r0 + 8) * ldc + gc) = p1;
            }
        }
    }
}

// ---------------- x -> hi/lo split (elementwise) ----------------------------
__global__ void split_x(const float4* __restrict__ x,
                        uint2* __restrict__ xh, uint2* __restrict__ xl)
{
    const size_t i = (size_t)blockIdx.x * blockDim.x + threadIdx.x;
    const float4 v = x[i];
    __nv_bfloat162 h01 = __float22bfloat162_rn(make_float2(v.x, v.y));
    __nv_bfloat162 h23 = __float22bfloat162_rn(make_float2(v.z, v.w));
    const float2 f01 = __bfloat1622float2(h01);
    const float2 f23 = __bfloat1622float2(h23);
    __nv_bfloat162 l01 = __float22bfloat162_rn(make_float2(v.x - f01.x, v.y - f01.y));
    __nv_bfloat162 l23 = __float22bfloat162_rn(make_float2(v.z - f23.x, v.w - f23.y));
    uint2 uh, ul;
    uh.x = *reinterpret_cast<uint32_t*>(&h01);
    uh.y = *reinterpret_cast<uint32_t*>(&h23);
    ul.x = *reinterpret_cast<uint32_t*>(&l01);
    ul.y = *reinterpret_cast<uint32_t*>(&l23);
    xh[i] = uh;
    xl[i] = ul;
}

// ---------------- weight prep: transpose [K,N] f32 -> [Np][Kp] bf16 hi/lo --
__global__ void prep_weight(const float* __restrict__ W, int K, int N,
                            bf16* __restrict__ Wh, bf16* __restrict__ Wl,
                            int Kp, int Np)
{
    __shared__ float t[32][33];
    const int k0 = blockIdx.x * 32, n0 = blockIdx.y * 32;
    const int tx = threadIdx.x, ty = threadIdx.y;     // (32, 8)
#pragma unroll
    for (int j = 0; j < 4; j++) {
        const int k = k0 + ty + j * 8, n = n0 + tx;
        t[ty + j * 8][tx] = (k < K && n < N) ? W[(size_t)k * N + n] : 0.0f;
    }
    __syncthreads();
#pragma unroll
    for (int j = 0; j < 4; j++) {
        const int n = n0 + ty + j * 8, k = k0 + tx;
        if (n < Np && k < Kp) {
            const float v = t[tx][ty + j * 8];
            const bf16 h = __float2bfloat16_rn(v);
            Wh[(size_t)n * Kp + k] = h;
            Wl[(size_t)n * Kp + k] = __float2bfloat16_rn(v - __bfloat162float(h));
        }
    }
}

// ------------- per-row heads: rho = tanh(h1@W22+b22), logs = h1@W23+b23 ----
__global__ void rho_logs_kernel(const bf16* __restrict__ h1h,
                                const bf16* __restrict__ h1l,
                                const float* __restrict__ W22,
                                const float* __restrict__ b22,
                                const float* __restrict__ W23,
                                const float* __restrict__ b23,
                                float* __restrict__ rho_out,
                                float* __restrict__ logs_out)
{
    const int row  = blockIdx.x * blockDim.y + threadIdx.y;
    const int lane = threadIdx.x;
    const size_t base = (size_t)row * H_PAD;

    float a = 0.f, b = 0.f;
    for (int i = lane; i < H_DIM; i += 32) {
        const float h = __bfloat162float(h1h[base + i]) + __bfloat162float(h1l[base + i]);
        a = fmaf(h, W22[i], a);
        b = fmaf(h, W23[i], b);
    }
#pragma unroll
    for (int o = 16; o > 0; o >>= 1) {
        a += __shfl_xor_sync(0xffffffffu, a, o);
        b += __shfl_xor_sync(0xffffffffu, b, o);
    }
    if (lane == 0) {
        const float logs = b + b23[0];
        rho_out[row]  = tanhf(a + b22[0]);
        logs_out[row] = logs;
        g_std[row]    = sqrtf(expf(logs));
    }
}

// ------------- z = cumsum(eps*std) + mu, stored as bf16 hi/lo --------------
__global__ void scan_kernel(const float* __restrict__ eps,
                            const float* __restrict__ mu,
                            bf16* __restrict__ zh, bf16* __restrict__ zl)
{
    const int row = blockIdx.x;
    const int t   = threadIdx.x;          // 0..511
    const float s = g_std[row];

    float v = eps[(size_t)row * Z_DIM + t] * s;
#pragma unroll
    for (int o = 1; o < 32; o <<= 1) {
        const float n = __shfl_up_sync(0xffffffffu, v, o);
        if ((t & 31) >= o) v += n;
    }
    __shared__ float ws[16];
    if ((t & 31) == 31) ws[t >> 5] = v;
    __syncthreads();
    if (t < 16) {
        float w = ws[t];
#pragma unroll
        for (int o = 1; o < 16; o <<= 1) {
            const float n = __shfl_up_sync(0x0000ffffu, w, o);
            if (t >= o) w += n;
        }
        ws[t] = w;
    }
    __syncthreads();
    if (t >= 32) v += ws[(t >> 5) - 1];

    v += mu[(size_t)row * Z_DIM + t];
    const bf16 h = __float2bfloat16_rn(v);
    zh[(size_t)row * Z_DIM + t] = h;
    zl[(size_t)row * Z_DIM + t] = __float2bfloat16_rn(v - __bfloat162float(h));
}

// ---------------------------------------------------------------------------
extern "C" void kernel_launch(void* const* d_in, const int* in_sizes, int n_in,
                              void* d_out, int out_size)
{
    const float* x   = (const float*)d_in[0];
    const float* eps = (const float*)d_in[1];
    const float* W1  = (const float*)d_in[2];
    const float* b1  = (const float*)d_in[3];
    const float* W21 = (const float*)d_in[4];
    const float* b21 = (const float*)d_in[5];
    const float* W22 = (const float*)d_in[6];
    const float* b22 = (const float*)d_in[7];
    const float* W23 = (const float*)d_in[8];
    const float* b23 = (const float*)d_in[9];
    const float* W3  = (const float*)d_in[10];
    const float* b3  = (const float*)d_in[11];
    const float* W4  = (const float*)d_in[12];
    const float* b4  = (const float*)d_in[13];

    float* out       = (float*)d_out;
    float* out_recon = out;                                    // [B, 4096]
    float* out_mu    = out_recon + (size_t)B_ROWS * DATA_DIM;  // [B, 512]
    float* out_rho   = out_mu    + (size_t)B_ROWS * Z_DIM;     // [B, 1]
    float* out_logs  = out_rho   + B_ROWS;                     // [B, 1]

    bf16 *xh, *xl, *h1h, *h1l, *zh, *zl, *h3h, *h3l;
    bf16 *W1h, *W1l, *W21h, *W21l, *W3h, *W3l, *W4h, *W4l;
    cudaGetSymbolAddress((void**)&xh,   g_xh);
    cudaGetSymbolAddress((void**)&xl,   g_xl);
    cudaGetSymbolAddress((void**)&h1h,  g_h1h);
    cudaGetSymbolAddress((void**)&h1l,  g_h1l);
    cudaGetSymbolAddress((void**)&zh,   g_zh);
    cudaGetSymbolAddress((void**)&zl,   g_zl);
    cudaGetSymbolAddress((void**)&h3h,  g_h3h);
    cudaGetSymbolAddress((void**)&h3l,  g_h3l);
    cudaGetSymbolAddress((void**)&W1h,  g_W1h);
    cudaGetSymbolAddress((void**)&W1l,  g_W1l);
    cudaGetSymbolAddress((void**)&W21h, g_W21h);
    cudaGetSymbolAddress((void**)&W21l, g_W21l);
    cudaGetSymbolAddress((void**)&W3h,  g_W3h);
    cudaGetSymbolAddress((void**)&W3l,  g_W3l);
    cudaGetSymbolAddress((void**)&W4h,  g_W4h);
    cudaGetSymbolAddress((void**)&W4l,  g_W4l);

    cudaFuncSetAttribute(gemm_mma<1, 1>, cudaFuncAttributeMaxDynamicSharedMemorySize, SMEM_TOT);
    cudaFuncSetAttribute(gemm_mma<0, 0>, cudaFuncAttributeMaxDynamicSharedMemorySize, SMEM_TOT);
    cudaFuncSetAttribute(gemm_mma<2, 0>, cudaFuncAttributeMaxDynamicSharedMemorySize, SMEM_TOT);

    // operand prep
    split_x<<<(B_ROWS * DATA_DIM / 4) / 256, 256>>>(
        (const float4*)x, (uint2*)xh, (uint2*)xl);
    const dim3 pb(32, 8);
    prep_weight<<<dim3(DATA_DIM / 32, N1_PAD / 32), pb>>>(W1,  DATA_DIM, H_DIM, W1h,  W1l,  DATA_DIM, N1_PAD);
    prep_weight<<<dim3(H_PAD / 32,    Z_DIM / 32),  pb>>>(W21, H_DIM,    Z_DIM, W21h, W21l, H_PAD,    Z_DIM);
    prep_weight<<<dim3(Z_DIM / 32,    N1_PAD / 32), pb>>>(W3,  Z_DIM,    H_DIM, W3h,  W3l,  Z_DIM,    N1_PAD);
    prep_weight<<<dim3(H_PAD / 32,  DATA_DIM / 32), pb>>>(W4,  H_DIM, DATA_DIM, W4h,  W4l,  H_PAD,    DATA_DIM);

    // 1) h1 = relu(x @ W1 + b1) -> hi/lo
    gemm_mma<1, 1><<<dim3(N1_PAD / 128, B_ROWS / 128), 256, SMEM_TOT>>>(
        xh, xl, DATA_DIM, W1h, W1l, DATA_DIM, b1,
        nullptr, h1h, h1l, H_PAD, H_DIM, DATA_DIM);

    // 2a) rho / logs / std
    rho_logs_kernel<<<B_ROWS / 8, dim3(32, 8)>>>(
        h1h, h1l, W22, b22, W23, b23, out_rho, out_logs);

    // 2b) mu = h1 @ W21 + b21 -> fp32 output
    gemm_mma<0, 0><<<dim3(Z_DIM / 128, B_ROWS / 128), 256, SMEM_TOT>>>(
        h1h, h1l, H_PAD, W21h, W21l, H_PAD, b21,
        out_mu, nullptr, nullptr, Z_DIM, Z_DIM, H_PAD);

    // 2c) z = cumsum(eps*std) + mu -> hi/lo
    scan_kernel<<<B_ROWS, Z_DIM>>>(eps, out_mu, zh, zl);

    // 3) h3 = relu(z @ W3 + b3) -> hi/lo
    gemm_mma<1, 1><<<dim3(N1_PAD / 128, B_ROWS / 128), 256, SMEM_TOT>>>(
        zh, zl, Z_DIM, W3h, W3l, Z_DIM, b3,
        nullptr, h3h, h3l, H_PAD, H_DIM, Z_DIM);

    // 4) recon = sigmoid(h3 @ W4 + b4) -> fp32 output
    gemm_mma<2, 0><<<dim3(DATA_DIM / 128, B_ROWS / 128), 256, SMEM_TOT>>>(
        h3h, h3l, H_PAD, W4h, W4l, H_PAD, b4,
        out_recon, nullptr, nullptr, DATA_DIM, DATA_DIM, H_PAD);
}

// round 7
// speedup vs baseline: 2.5066x; 1.1533x over previous
#include <cuda_runtime.h>
#include <cuda_bf16.h>
#include <cstdint>
#include <math.h>

#define B_ROWS   16384
#define DATA_DIM 4096
#define Z_DIM    512
#define H_DIM    400
#define H_PAD    448     // H padded to multiple of 64 (K use)
#define N1_PAD   512     // H padded to multiple of 128 (N-tile use)

typedef __nv_bfloat16 bf16;

// ---------------- scratch (allocation-free device globals, zero-init) ------
__device__ alignas(256) bf16 g_xh [B_ROWS * DATA_DIM];
__device__ alignas(256) bf16 g_xl [B_ROWS * DATA_DIM];
__device__ alignas(256) bf16 g_h1h[B_ROWS * H_PAD];    // pad cols stay zero
__device__ alignas(256) bf16 g_h1l[B_ROWS * H_PAD];
__device__ alignas(256) bf16 g_zh [B_ROWS * Z_DIM];
__device__ alignas(256) bf16 g_zl [B_ROWS * Z_DIM];
__device__ alignas(256) bf16 g_h3h[B_ROWS * H_PAD];
__device__ alignas(256) bf16 g_h3l[B_ROWS * H_PAD];
__device__ float g_std[B_ROWS];
// transposed + split weights [Npad][Kpad] bf16 (K-major), zero padded
__device__ alignas(256) bf16 g_W1h [N1_PAD * DATA_DIM], g_W1l [N1_PAD * DATA_DIM];
__device__ alignas(256) bf16 g_W21h[Z_DIM * H_PAD],     g_W21l[Z_DIM * H_PAD];
__device__ alignas(256) bf16 g_W3h [N1_PAD * Z_DIM],    g_W3l [N1_PAD * Z_DIM];
__device__ alignas(256) bf16 g_W4h [DATA_DIM * H_PAD],  g_W4l [DATA_DIM * H_PAD];

// ---------------- PTX helpers ----------------------------------------------
__device__ __forceinline__ uint32_t smem_u32(const void* p) {
    uint32_t a;
    asm("{ .reg .u64 t; cvta.to.shared.u64 t, %1; cvt.u32.u64 %0, t; }"
        : "=r"(a) : "l"(p));
    return a;
}
__device__ __forceinline__ void cp16(uint32_t dst, const void* src) {
    asm volatile("cp.async.cg.shared.global [%0], [%1], 16;"
                 :: "r"(dst), "l"(src) : "memory");
}
__device__ __forceinline__ void cp_commit() {
    asm volatile("cp.async.commit_group;" ::: "memory");
}
template <int N> __device__ __forceinline__ void cp_wait() {
    asm volatile("cp.async.wait_group %0;" :: "n"(N) : "memory");
}
#define LDSM4(R, addr) \
    asm volatile("ldmatrix.sync.aligned.m8n8.x4.shared.b16 {%0,%1,%2,%3}, [%4];" \
                 : "=r"((R)[0]), "=r"((R)[1]), "=r"((R)[2]), "=r"((R)[3])      \
                 : "r"(addr))
#define MMA16816(C, A, B0, B1) \
    asm volatile("mma.sync.aligned.m16n8k16.row.col.f32.bf16.bf16.f32 "        \
                 "{%0,%1,%2,%3}, {%4,%5,%6,%7}, {%8,%9}, {%0,%1,%2,%3};"       \
                 : "+f"((C)[0]), "+f"((C)[1]), "+f"((C)[2]), "+f"((C)[3])      \
                 : "r"((A)[0]), "r"((A)[1]), "r"((A)[2]), "r"((A)[3]),         \
                   "r"(B0), "r"(B1))

// smem stage: 4 matrices [128 rows][64 bf16 + 8 pad] (144 B rows, 16B aligned)
#define ROWB     144
#define MAT_SZ   18432                 // 128*144
#define OFF_AH   0
#define OFF_AL   18432
#define OFF_BH   36864
#define OFF_BL   55296
#define STAGE_SZ 73728
#define SMEM_TOT (2 * STAGE_SZ)       // 147456

// ---------------- stage loader: K-chunk 64, cp.async 16B ------------------
__device__ __forceinline__ void ld_stage(
    uint32_t s0, int tid,
    const bf16* __restrict__ Ah, const bf16* __restrict__ Al,
    size_t arow0, int lda,
    const bf16* __restrict__ Bh, const bf16* __restrict__ Bl,
    size_t brow0, int ldb, int k0)
{
#pragma unroll
    for (int j = 0; j < 16; j++) {
        const int idx = tid + j * 256;          // 0..4095
        const int mat = idx >> 10;              // 0:Ah 1:Al 2:Bh 3:Bl
        const int rem = idx & 1023;
        const int row = rem >> 3;               // 0..127
        const int ch  = rem & 7;                // 16B chunk (8 bf16)
        const bf16* src;
        if (mat == 0)      src = Ah + (arow0 + row) * (size_t)lda + k0 + ch * 8;
        else if (mat == 1) src = Al + (arow0 + row) * (size_t)lda + k0 + ch * 8;
        else if (mat == 2) src = Bh + (brow0 + row) * (size_t)ldb + k0 + ch * 8;
        else               src = Bl + (brow0 + row) * (size_t)ldb + k0 + ch * 8;
        cp16(s0 + mat * MAT_SZ + row * ROWB + ch * 16, src);
    }
}

// ---------------- split-bf16 tensor-core GEMM ------------------------------
// C[128*by.., 128*bx..] = epi(A @ B^T + bias)
// A: bf16 hi/lo [M][lda] row-major; B: bf16 hi/lo [Npad][ldb] K-major.
// EPI: 0 none, 1 relu, 2 sigmoid.  SPLIT: 1 -> store hi/lo bf16, 0 -> fp32.
template <int EPI, int SPLIT>
__global__ __launch_bounds__(256) void gemm_mma(
    const bf16* __restrict__ Ah, const bf16* __restrict__ Al, int lda,
    const bf16* __restrict__ Bh, const bf16* __restrict__ Bl, int ldb,
    const float* __restrict__ bias,
    float* __restrict__ Cf, bf16* __restrict__ Ch, bf16* __restrict__ Cl,
    int ldc, int nout, int K)
{
    extern __shared__ char smem[];
    const uint32_t sb = smem_u32(smem);
    const int tid  = threadIdx.x;
    const int wid  = tid >> 5, lane = tid & 31;
    const int wm   = wid & 1,  wn   = wid >> 1;   // 2 M-warps x 4 N-warps
    const int bx   = blockIdx.x, by = blockIdx.y;
    const size_t arow0 = (size_t)by * 128;
    const size_t brow0 = (size_t)bx * 128;

    float acc[4][4][4];
#pragma unroll
    for (int a = 0; a < 4; a++)
#pragma unroll
        for (int b = 0; b < 4; b++)
#pragma unroll
            for (int c = 0; c < 4; c++) acc[a][b][c] = 0.0f;

    const int NC = K >> 6;                        // 64-wide K chunks
    ld_stage(sb, tid, Ah, Al, arow0, lda, Bh, Bl, brow0, ldb, 0);
    cp_commit();

    for (int i = 0; i < NC; i++) {
        if (i + 1 < NC) {
            ld_stage(sb + ((i + 1) & 1) * STAGE_SZ, tid,
                     Ah, Al, arow0, lda, Bh, Bl, brow0, ldb, (i + 1) << 6);
            cp_commit();
            cp_wait<1>();
        } else {
            cp_wait<0>();
        }
        __syncthreads();

        const uint32_t st = sb + (i & 1) * STAGE_SZ;
#pragma unroll
        for (int ks = 0; ks < 4; ks++) {
            uint32_t ah[4][4], al[4][4], bh[4][2], bl[4][2];
#pragma unroll
            for (int mt = 0; mt < 4; mt++) {
                const int row = wm * 64 + mt * 16 + (lane & 15);
                const uint32_t aoff = row * ROWB + ks * 32 + ((lane >> 4) << 4);
                LDSM4(ah[mt], st + OFF_AH + aoff);
                LDSM4(al[mt], st + OFF_AL + aoff);
            }
#pragma unroll
            for (int nt = 0; nt < 2; nt++) {
                const int row = wn * 32 + nt * 16 + (lane & 7) + ((lane >> 4) << 3);
                const uint32_t boff = row * ROWB + ks * 32 + ((lane >> 3) & 1) * 16;
                uint32_t r[4];
                LDSM4(r, st + OFF_BH + boff);
                bh[nt * 2][0] = r[0]; bh[nt * 2][1] = r[1];
                bh[nt * 2 + 1][0] = r[2]; bh[nt * 2 + 1][1] = r[3];
                LDSM4(r, st + OFF_BL + boff);
                bl[nt * 2][0] = r[0]; bl[nt * 2][1] = r[1];
                bl[nt * 2 + 1][0] = r[2]; bl[nt * 2 + 1][1] = r[3];
            }
#pragma unroll
            for (int mt = 0; mt < 4; mt++)
#pragma unroll
                for (int n = 0; n < 4; n++) {
                    MMA16816(acc[mt][n], ah[mt], bh[n][0], bh[n][1]);
                    MMA16816(acc[mt][n], al[mt], bh[n][0], bh[n][1]);
                    MMA16816(acc[mt][n], ah[mt], bl[n][0], bl[n][1]);
                }
        }
        __syncthreads();
    }

    // ---- epilogue: bias + activation, direct register stores ----
#pragma unroll
    for (int n8 = 0; n8 < 4; n8++) {
        const int gc = bx * 128 + wn * 32 + n8 * 8 + (lane & 3) * 2;
        if (gc >= nout) continue;
        const float bia0 = bias[gc], bia1 = bias[gc + 1];
#pragma unroll
        for (int mt = 0; mt < 4; mt++) {
            const size_t r0 = arow0 + wm * 64 + mt * 16 + (lane >> 2);
            float v[4];
            v[0] = acc[mt][n8][0] + bia0;  v[1] = acc[mt][n8][1] + bia1;
            v[2] = acc[mt][n8][2] + bia0;  v[3] = acc[mt][n8][3] + bia1;
#pragma unroll
            for (int q = 0; q < 4; q++) {
                if (EPI == 1) v[q] = fmaxf(v[q], 0.0f);
                if (EPI == 2) v[q] = 1.0f / (1.0f + __expf(-v[q]));
            }
            if (SPLIT) {
                bf16 h0 = __float2bfloat16_rn(v[0]);
                bf16 h1 = __float2bfloat16_rn(v[1]);
                bf16 h2 = __float2bfloat16_rn(v[2]);
                bf16 h3 = __float2bfloat16_rn(v[3]);
                __nv_bfloat162 hp0, hp1, lp0, lp1;
                hp0.x = h0; hp0.y = h1;  hp1.x = h2; hp1.y = h3;
                lp0.x = __float2bfloat16_rn(v[0] - __bfloat162float(h0));
                lp0.y = __float2bfloat16_rn(v[1] - __bfloat162float(h1));
                lp1.x = __float2bfloat16_rn(v[2] - __bfloat162float(h2));
                lp1.y = __float2bfloat16_rn(v[3] - __bfloat162float(h3));
                *reinterpret_cast<__nv_bfloat162*>(Ch + r0 * ldc + gc)       = hp0;
                *reinterpret_cast<__nv_bfloat162*>(Cl + r0 * ldc + gc)       = lp0;
                *reinterpret_cast<__nv_bfloat162*>(Ch + (r0 + 8) * ldc + gc) = hp1;
                *reinterpret_cast<__nv_bfloat162*>(Cl + (r0 + 8) * ldc + gc) = lp1;
            } else {
                float2 p0, p1;
                p0.x = v[0]; p0.y = v[1];  p1.x = v[2]; p1.y = v[3];
                *reinterpret_cast<float2*>(Cf + r0 * ldc + gc)       = p0;
                *reinterpret_cast<float2*>(Cf + (r0 + 8) * ldc + gc) = p1;
            }
        }
    }
}

// ---------------- x -> hi/lo split (elementwise) ----------------------------
__global__ void split_x(const float4* __restrict__ x,
                        uint2* __restrict__ xh, uint2* __restrict__ xl)
{
    const size_t i = (size_t)blockIdx.x * blockDim.x + threadIdx.x;
    const float4 v = x[i];
    __nv_bfloat162 h01 = __float22bfloat162_rn(make_float2(v.x, v.y));
    __nv_bfloat162 h23 = __float22bfloat162_rn(make_float2(v.z, v.w));
    const float2 f01 = __bfloat1622float2(h01);
    const float2 f23 = __bfloat1622float2(h23);
    __nv_bfloat162 l01 = __float22bfloat162_rn(make_float2(v.x - f01.x, v.y - f01.y));
    __nv_bfloat162 l23 = __float22bfloat162_rn(make_float2(v.z - f23.x, v.w - f23.y));
    uint2 uh, ul;
    uh.x = *reinterpret_cast<uint32_t*>(&h01);
    uh.y = *reinterpret_cast<uint32_t*>(&h23);
    ul.x = *reinterpret_cast<uint32_t*>(&l01);
    ul.y = *reinterpret_cast<uint32_t*>(&l23);
    xh[i] = uh;
    xl[i] = ul;
}

// ---------------- weight prep: transpose [K,N] f32 -> [Np][Kp] bf16 hi/lo --
__global__ void prep_weight(const float* __restrict__ W, int K, int N,
                            bf16* __restrict__ Wh, bf16* __restrict__ Wl,
                            int Kp, int Np)
{
    __shared__ float t[32][33];
    const int k0 = blockIdx.x * 32, n0 = blockIdx.y * 32;
    const int tx = threadIdx.x, ty = threadIdx.y;     // (32, 8)
#pragma unroll
    for (int j = 0; j < 4; j++) {
        const int k = k0 + ty + j * 8, n = n0 + tx;
        t[ty + j * 8][tx] = (k < K && n < N) ? W[(size_t)k * N + n] : 0.0f;
    }
    __syncthreads();
#pragma unroll
    for (int j = 0; j < 4; j++) {
        const int n = n0 + ty + j * 8, k = k0 + tx;
        if (n < Np && k < Kp) {
            const float v = t[tx][ty + j * 8];
            const bf16 h = __float2bfloat16_rn(v);
            Wh[(size_t)n * Kp + k] = h;
            Wl[(size_t)n * Kp + k] = __float2bfloat16_rn(v - __bfloat162float(h));
        }
    }
}

// ------------- per-row heads: rho = tanh(h1@W22+b22), logs = h1@W23+b23 ----
__global__ void rho_logs_kernel(const bf16* __restrict__ h1h,
                                const bf16* __restrict__ h1l,
                                const float* __restrict__ W22,
                                const float* __restrict__ b22,
                                const float* __restrict__ W23,
                                const float* __restrict__ b23,
                                float* __restrict__ rho_out,
                                float* __restrict__ logs_out)
{
    const int row  = blockIdx.x * blockDim.y + threadIdx.y;
    const int lane = threadIdx.x;
    const size_t base = (size_t)row * H_PAD;

    float a = 0.f, b = 0.f;
    for (int i = lane; i < H_DIM; i += 32) {
        const float h = __bfloat162float(h1h[base + i]) + __bfloat162float(h1l[base + i]);
        a = fmaf(h, W22[i], a);
        b = fmaf(h, W23[i], b);
    }
#pragma unroll
    for (int o = 16; o > 0; o >>= 1) {
        a += __shfl_xor_sync(0xffffffffu, a, o);
        b += __shfl_xor_sync(0xffffffffu, b, o);
    }
    if (lane == 0) {
        const float logs = b + b23[0];
        rho_out[row]  = tanhf(a + b22[0]);
        logs_out[row] = logs;
        g_std[row]    = sqrtf(expf(logs));
    }
}

// ------------- z = cumsum(eps*std) + mu, warp per row, bf16 hi/lo ----------
__global__ __launch_bounds__(256) void scan_kernel(
    const float* __restrict__ eps, const float* __restrict__ mu,
    bf16* __restrict__ zh, bf16* __restrict__ zl)
{
    const int warp = threadIdx.x >> 5, lane = threadIdx.x & 31;
    const int row  = blockIdx.x * 8 + warp;
    const float s  = g_std[row];
    const size_t base = (size_t)row * Z_DIM + lane * 16;

    float v[16];
#pragma unroll
    for (int q = 0; q < 4; q++) {
        const float4 e = *reinterpret_cast<const float4*>(eps + base + q * 4);
        v[q * 4 + 0] = e.x * s;  v[q * 4 + 1] = e.y * s;
        v[q * 4 + 2] = e.z * s;  v[q * 4 + 3] = e.w * s;
    }
    // serial inclusive prefix over the 16 local values
#pragma unroll
    for (int q = 1; q < 16; q++) v[q] += v[q - 1];
    // exclusive warp scan of per-lane totals
    float tot = v[15];
#pragma unroll
    for (int o = 1; o < 32; o <<= 1) {
        const float n = __shfl_up_sync(0xffffffffu, tot, o);
        if (lane >= o) tot += n;
    }
    const float off = tot - v[15];        // exclusive prefix for this lane

    __nv_bfloat162 hp[8], lp[8];
#pragma unroll
    for (int q = 0; q < 4; q++) {
        const float4 m = *reinterpret_cast<const float4*>(mu + base + q * 4);
        float w0 = v[q * 4 + 0] + off + m.x;
        float w1 = v[q * 4 + 1] + off + m.y;
        float w2 = v[q * 4 + 2] + off + m.z;
        float w3 = v[q * 4 + 3] + off + m.w;
        bf16 h0 = __float2bfloat16_rn(w0), h1 = __float2bfloat16_rn(w1);
        bf16 h2 = __float2bfloat16_rn(w2), h3 = __float2bfloat16_rn(w3);
        hp[q * 2].x = h0;     hp[q * 2].y = h1;
        hp[q * 2 + 1].x = h2; hp[q * 2 + 1].y = h3;
        lp[q * 2].x = __float2bfloat16_rn(w0 - __bfloat162float(h0));
        lp[q * 2].y = __float2bfloat16_rn(w1 - __bfloat162float(h1));
        lp[q * 2 + 1].x = __float2bfloat16_rn(w2 - __bfloat162float(h2));
        lp[q * 2 + 1].y = __float2bfloat16_rn(w3 - __bfloat162float(h3));
    }
    *reinterpret_cast<uint4*>(zh + base)     = *reinterpret_cast<uint4*>(&hp[0]);
    *reinterpret_cast<uint4*>(zh + base + 8) = *reinterpret_cast<uint4*>(&hp[4]);
    *reinterpret_cast<uint4*>(zl + base)     = *reinterpret_cast<uint4*>(&lp[0]);
    *reinterpret_cast<uint4*>(zl + base + 8) = *reinterpret_cast<uint4*>(&lp[4]);
}

// ---------------------------------------------------------------------------
extern "C" void kernel_launch(void* const* d_in, const int* in_sizes, int n_in,
                              void* d_out, int out_size)
{
    const float* x   = (const float*)d_in[0];
    const float* eps = (const float*)d_in[1];
    const float* W1  = (const float*)d_in[2];
    const float* b1  = (const float*)d_in[3];
    const float* W21 = (const float*)d_in[4];
    const float* b21 = (const float*)d_in[5];
    const float* W22 = (const float*)d_in[6];
    const float* b22 = (const float*)d_in[7];
    const float* W23 = (const float*)d_in[8];
    const float* b23 = (const float*)d_in[9];
    const float* W3  = (const float*)d_in[10];
    const float* b3  = (const float*)d_in[11];
    const float* W4  = (const float*)d_in[12];
    const float* b4  = (const float*)d_in[13];

    float* out       = (float*)d_out;
    float* out_recon = out;                                    // [B, 4096]
    float* out_mu    = out_recon + (size_t)B_ROWS * DATA_DIM;  // [B, 512]
    float* out_rho   = out_mu    + (size_t)B_ROWS * Z_DIM;     // [B, 1]
    float* out_logs  = out_rho   + B_ROWS;                     // [B, 1]

    bf16 *xh, *xl, *h1h, *h1l, *zh, *zl, *h3h, *h3l;
    bf16 *W1h, *W1l, *W21h, *W21l, *W3h, *W3l, *W4h, *W4l;
    cudaGetSymbolAddress((void**)&xh,   g_xh);
    cudaGetSymbolAddress((void**)&xl,   g_xl);
    cudaGetSymbolAddress((void**)&h1h,  g_h1h);
    cudaGetSymbolAddress((void**)&h1l,  g_h1l);
    cudaGetSymbolAddress((void**)&zh,   g_zh);
    cudaGetSymbolAddress((void**)&zl,   g_zl);
    cudaGetSymbolAddress((void**)&h3h,  g_h3h);
    cudaGetSymbolAddress((void**)&h3l,  g_h3l);
    cudaGetSymbolAddress((void**)&W1h,  g_W1h);
    cudaGetSymbolAddress((void**)&W1l,  g_W1l);
    cudaGetSymbolAddress((void**)&W21h, g_W21h);
    cudaGetSymbolAddress((void**)&W21l, g_W21l);
    cudaGetSymbolAddress((void**)&W3h,  g_W3h);
    cudaGetSymbolAddress((void**)&W3l,  g_W3l);
    cudaGetSymbolAddress((void**)&W4h,  g_W4h);
    cudaGetSymbolAddress((void**)&W4l,  g_W4l);

    cudaFuncSetAttribute(gemm_mma<1, 1>, cudaFuncAttributeMaxDynamicSharedMemorySize, SMEM_TOT);
    cudaFuncSetAttribute(gemm_mma<0, 0>, cudaFuncAttributeMaxDynamicSharedMemorySize, SMEM_TOT);
    cudaFuncSetAttribute(gemm_mma<2, 0>, cudaFuncAttributeMaxDynamicSharedMemorySize, SMEM_TOT);

    const dim3 pb(32, 8);

    // idx0: x -> hi/lo
    split_x<<<(B_ROWS * DATA_DIM / 4) / 256, 256>>>(
        (const float4*)x, (uint2*)xh, (uint2*)xl);
    // idx1, idx2: weights needed by gemm1/gemm2
    prep_weight<<<dim3(DATA_DIM / 32, N1_PAD / 32), pb>>>(W1,  DATA_DIM, H_DIM, W1h,  W1l,  DATA_DIM, N1_PAD);
    prep_weight<<<dim3(H_PAD / 32,    Z_DIM / 32),  pb>>>(W21, H_DIM,    Z_DIM, W21h, W21l, H_PAD,    Z_DIM);

    // idx3 (ncu capture slot): h1 = relu(x @ W1 + b1) -> hi/lo
    gemm_mma<1, 1><<<dim3(N1_PAD / 128, B_ROWS / 128), 256, SMEM_TOT>>>(
        xh, xl, DATA_DIM, W1h, W1l, DATA_DIM, b1,
        nullptr, h1h, h1l, H_PAD, H_DIM, DATA_DIM);

    // idx4: rho / logs / std
    rho_logs_kernel<<<B_ROWS / 8, dim3(32, 8)>>>(
        h1h, h1l, W22, b22, W23, b23, out_rho, out_logs);

    // idx5: mu = h1 @ W21 + b21 -> fp32 output
    gemm_mma<0, 0><<<dim3(Z_DIM / 128, B_ROWS / 128), 256, SMEM_TOT>>>(
        h1h, h1l, H_PAD, W21h, W21l, H_PAD, b21,
        out_mu, nullptr, nullptr, Z_DIM, Z_DIM, H_PAD);

    // idx6: z = cumsum(eps*std) + mu -> hi/lo (warp per row)
    scan_kernel<<<B_ROWS / 8, 256>>>(eps, out_mu, zh, zl);

    // idx7: W3 prep, idx8: h3 = relu(z @ W3 + b3) -> hi/lo
    prep_weight<<<dim3(Z_DIM / 32, N1_PAD / 32), pb>>>(W3, Z_DIM, H_DIM, W3h, W3l, Z_DIM, N1_PAD);
    gemm_mma<1, 1><<<dim3(N1_PAD / 128, B_ROWS / 128), 256, SMEM_TOT>>>(
        zh, zl, Z_DIM, W3h, W3l, Z_DIM, b3,
        nullptr, h3h, h3l, H_PAD, H_DIM, Z_DIM);

    // idx9: W4 prep, idx10: recon = sigmoid(h3 @ W4 + b4) -> fp32 output
    prep_weight<<<dim3(H_PAD / 32, DATA_DIM / 32), pb>>>(W4, H_DIM, DATA_DIM, W4h, W4l, H_PAD, DATA_DIM);
    gemm_mma<2, 0><<<dim3(DATA_DIM / 128, B_ROWS / 128), 256, SMEM_TOT>>>(
        h3h, h3l, H_PAD, W4h, W4l, H_PAD, b4,
        out_recon, nullptr, nullptr, DATA_DIM, DATA_DIM, H_PAD);
}